// round 1
// baseline (speedup 1.0000x reference)
#include <cuda_runtime.h>
#include <cuda_bf16.h>

// Problem constants
#define BSZ 4
#define NS  1024
#define D   2048
#define H   16
#define DH  128
#define SEQ (BSZ*NS)          // 4096
#define E3  (3*D)             // 6144
#define SCALE 0.08838834764831845f   // DH^-0.5
#define NEG_BIAS (-1e9f)

// ---------------- scratch (global device arrays; no allocations) -------------
__device__ float g_qkv[SEQ * E3];          // [4096, 6144]  (c,h,dh) packed: e = c*2048 + h*128 + dh
__device__ float g_S[(long)BSZ * H * NS * NS];   // [64, 1024, 1024] scores / probs
__device__ float g_ctx[SEQ * D];           // [4096, 2048]  context, layout [b,s][h*128+dh]

// ---------------- generic tiled SGEMM ----------------------------------------
// C[M,N] = A[M,K] * B, where
//   A is K-contiguous with leading dim lda
//   B_NN=false: B is [N,K] K-contiguous (NT),  ldb = row stride
//   B_NN=true : B is [K,N] N-contiguous (NN),  ldb = row stride
// Batched via blockIdx.z: z = outer*hdiv + inner, offsets (aOuter,aInner) etc.
// EPI: 0 = plain, 1 = +bias[col], 2 = (acc + ids[col]*-1e9)*scale
#define BM 128
#define BN 128
#define BK 16
#define TM 8
#define TN 8

template<bool B_NN, int EPI>
__global__ __launch_bounds__(256, 2)
void sgemm_kernel(const float* __restrict__ A,
                  const float* __restrict__ B,
                  float* __restrict__ C,
                  int K, int lda, int ldb, int ldc,
                  long aOuter, long aInner,
                  long bOuter, long bInner,
                  long cOuter, long cInner,
                  int hdiv,
                  const float* __restrict__ bias,
                  const int* __restrict__ ids, int idsStride)
{
    __shared__ float As[BK][BM];
    __shared__ float Bs[BK][BN];

    const int z  = blockIdx.z;
    const int bo = z / hdiv;
    const int hi = z - bo * hdiv;
    A += (long)bo * aOuter + (long)hi * aInner;
    B += (long)bo * bOuter + (long)hi * bInner;
    C += (long)bo * cOuter + (long)hi * cInner;
    if (EPI == 2) ids += (long)bo * idsStride;

    const int tid = threadIdx.x;
    const int tx = tid & 15;        // column group (N)
    const int ty = tid >> 4;        // row group (M)
    const int m0 = blockIdx.y * BM;
    const int n0 = blockIdx.x * BN;

    float acc[TM][TN];
    #pragma unroll
    for (int i = 0; i < TM; i++)
        #pragma unroll
        for (int j = 0; j < TN; j++)
            acc[i][j] = 0.f;

    const int nK = K / BK;
    for (int kt = 0; kt < nK; kt++) {
        const int k0 = kt * BK;

        // load A tile [BM x BK] -> As[k][m] (transposed)
        #pragma unroll
        for (int i = 0; i < 2; i++) {
            int slot = tid + i * 256;          // 512 float4 slots
            int row  = slot >> 2;              // 0..127
            int k4   = (slot & 3) * 4;         // 0,4,8,12
            float4 v = *(const float4*)(A + (long)(m0 + row) * lda + k0 + k4);
            As[k4 + 0][row] = v.x;
            As[k4 + 1][row] = v.y;
            As[k4 + 2][row] = v.z;
            As[k4 + 3][row] = v.w;
        }
        // load B tile
        if (!B_NN) {
            #pragma unroll
            for (int i = 0; i < 2; i++) {
                int slot = tid + i * 256;
                int row  = slot >> 2;          // N index 0..127
                int k4   = (slot & 3) * 4;
                float4 v = *(const float4*)(B + (long)(n0 + row) * ldb + k0 + k4);
                Bs[k4 + 0][row] = v.x;
                Bs[k4 + 1][row] = v.y;
                Bs[k4 + 2][row] = v.z;
                Bs[k4 + 3][row] = v.w;
            }
        } else {
            #pragma unroll
            for (int i = 0; i < 2; i++) {
                int slot = tid + i * 256;
                int row  = slot >> 5;          // K index 0..15
                int c4   = (slot & 31) * 4;    // 0..124
                float4 v = *(const float4*)(B + (long)(k0 + row) * ldb + n0 + c4);
                *(float4*)&Bs[row][c4] = v;
            }
        }
        __syncthreads();

        #pragma unroll
        for (int k = 0; k < BK; k++) {
            float ar[TM], br[TN];
            #pragma unroll
            for (int i = 0; i < TM; i++) ar[i] = As[k][ty * TM + i];
            #pragma unroll
            for (int j = 0; j < TN; j++) br[j] = Bs[k][tx * TN + j];
            #pragma unroll
            for (int i = 0; i < TM; i++)
                #pragma unroll
                for (int j = 0; j < TN; j++)
                    acc[i][j] = fmaf(ar[i], br[j], acc[i][j]);
        }
        __syncthreads();
    }

    // epilogue
    #pragma unroll
    for (int i = 0; i < TM; i++) {
        int row = m0 + ty * TM + i;
        float* cp = C + (long)row * ldc + n0 + tx * TN;
        float vals[TN];
        #pragma unroll
        for (int j = 0; j < TN; j++) {
            float v = acc[i][j];
            if (EPI == 1) v += bias[n0 + tx * TN + j];
            if (EPI == 2) v = (v + (float)ids[n0 + tx * TN + j] * NEG_BIAS) * SCALE;
            vals[j] = v;
        }
        *(float4*)(cp + 0) = make_float4(vals[0], vals[1], vals[2], vals[3]);
        *(float4*)(cp + 4) = make_float4(vals[4], vals[5], vals[6], vals[7]);
    }
}

// ---------------- row softmax over 1024 columns -------------------------------
__global__ __launch_bounds__(256)
void softmax_kernel(float* __restrict__ S)
{
    const long row = blockIdx.x;
    float* p = S + row * (long)NS;
    const int tid = threadIdx.x;
    const int lane = tid & 31, wid = tid >> 5;

    float4 v = ((const float4*)p)[tid];

    // max reduce
    float mx = fmaxf(fmaxf(v.x, v.y), fmaxf(v.z, v.w));
    #pragma unroll
    for (int o = 16; o; o >>= 1) mx = fmaxf(mx, __shfl_xor_sync(0xffffffffu, mx, o));
    __shared__ float red[8];
    if (lane == 0) red[wid] = mx;
    __syncthreads();
    float m = red[0];
    #pragma unroll
    for (int i = 1; i < 8; i++) m = fmaxf(m, red[i]);

    // exp
    float4 e;
    e.x = __expf(v.x - m);
    e.y = __expf(v.y - m);
    e.z = __expf(v.z - m);
    e.w = __expf(v.w - m);

    // sum reduce
    float s = e.x + e.y + e.z + e.w;
    #pragma unroll
    for (int o = 16; o; o >>= 1) s += __shfl_xor_sync(0xffffffffu, s, o);
    __syncthreads();
    if (lane == 0) red[wid] = s;
    __syncthreads();
    float tot = red[0];
    #pragma unroll
    for (int i = 1; i < 8; i++) tot += red[i];

    float inv = 1.0f / tot;
    e.x *= inv; e.y *= inv; e.z *= inv; e.w *= inv;
    ((float4*)p)[tid] = e;
}

// ---------------- launch ------------------------------------------------------
extern "C" void kernel_launch(void* const* d_in, const int* in_sizes, int n_in,
                              void* d_out, int out_size)
{
    const float* x     = (const float*)d_in[0];   // [4,1024,2048]
    const int*   ids   = (const int*)  d_in[1];   // [4,1024]
    const float* w_in  = (const float*)d_in[2];   // [6144,2048]
    const float* w_out = (const float*)d_in[3];   // [2048,2048]
    const float* b_out = (const float*)d_in[4];   // [2048]
    float* out = (float*)d_out;                   // [4,1024,2048]

    void *p_qkv, *p_S, *p_ctx;
    cudaGetSymbolAddress(&p_qkv, g_qkv);
    cudaGetSymbolAddress(&p_S,   g_S);
    cudaGetSymbolAddress(&p_ctx, g_ctx);
    float* qkv = (float*)p_qkv;
    float* S   = (float*)p_S;
    float* ctx = (float*)p_ctx;

    // K1: QKV = x @ w_in^T              [4096,6144] = [4096,2048] x [6144,2048]^T
    sgemm_kernel<false, 0><<<dim3(E3 / BN, SEQ / BM, 1), 256>>>(
        x, w_in, qkv, D, D, D, E3,
        0, 0, 0, 0, 0, 0, 1, nullptr, nullptr, 0);

    // K2: S[b,h] = (Q K^T + mask) * scale   batched 64x: [1024,1024] = [1024,128] x [1024,128]^T
    sgemm_kernel<false, 2><<<dim3(NS / BN, NS / BM, BSZ * H), 256>>>(
        qkv /*Q: chunk 0*/, qkv + D /*K: chunk 1*/, S,
        DH, E3, E3, NS,
        (long)NS * E3, DH,           // A: per-batch, per-head offsets
        (long)NS * E3, DH,           // B
        (long)H * NS * NS, (long)NS * NS,   // C
        H, nullptr, ids, NS);

    // K3: row softmax
    softmax_kernel<<<BSZ * H * NS, 256>>>(S);

    // K4: ctx[b,h] = P @ V   batched 64x: [1024,128] = [1024,1024] x [1024,128]
    sgemm_kernel<true, 0><<<dim3(DH / BN, NS / BM, BSZ * H), 256>>>(
        S, qkv + 2 * D /*V: chunk 2*/, ctx,
        NS, NS, E3, D,
        (long)H * NS * NS, (long)NS * NS,  // A (probs)
        (long)NS * E3, DH,                 // B (V)
        (long)NS * D, DH,                  // C (ctx at [b,s][h*128+dh])
        H, nullptr, nullptr, 0);

    // K5: out = ctx @ w_out^T + b_out     [4096,2048] = [4096,2048] x [2048,2048]^T
    sgemm_kernel<false, 1><<<dim3(D / BN, SEQ / BM, 1), 256>>>(
        ctx, w_out, out, D, D, D, D,
        0, 0, 0, 0, 0, 0, 1, b_out, nullptr, 0);
}

// round 5
// speedup vs baseline: 2.6628x; 2.6628x over previous
#include <cuda_runtime.h>
#include <cuda_bf16.h>
#include <cstdint>

// Problem constants
#define BSZ 4
#define NS  1024
#define D   2048
#define H   16
#define DH  128
#define SEQ (BSZ*NS)          // 4096
#define E3  (3*D)             // 6144
#define SCALE 0.08838834764831845f   // DH^-0.5
#define NEG_BIAS (-1e9f)

// ---------------- scratch (global device arrays; no allocations) -------------
__device__ float g_qkv[SEQ * E3];                 // [4096, 6144]
__device__ float g_S[(long)BSZ * H * NS * NS];    // [64, 1024, 1024]
__device__ float g_ctx[SEQ * D];                  // [4096, 2048]

// tf32 round: PTX cvt.rna.tf32.f32 writes a .b32 register
__device__ __forceinline__ uint32_t to_tf32(float x) {
    uint32_t r;
    asm("cvt.rna.tf32.f32 %0, %1;" : "=r"(r) : "f"(x));
    return r;
}

// ---------------- tf32 tensor-core GEMM ---------------------------------------
// C[M,N] = A[M,K] * B
//   A: K-contiguous, leading dim lda
//   B_NN=false: B is [N,K] K-contiguous (NT), ldb = row stride
//   B_NN=true : B is [K,N] N-contiguous (NN), ldb = row stride
// Batched via blockIdx.z = bo*hdiv + hi with (outer, inner) offsets.
// EPI: 0 plain, 1 +bias[col], 2 (acc + ids[col]*-1e9)*scale
#define BM 128
#define BN 128
#define BK 32
#define SKA (BK + 4)   // smem row stride (floats)

template<bool B_NN, int EPI>
__global__ __launch_bounds__(256)
void tgemm_kernel(const float* __restrict__ A,
                  const float* __restrict__ B,
                  float* __restrict__ C,
                  int K, int lda, int ldb, int ldc,
                  long aOuter, long aInner,
                  long bOuter, long bInner,
                  long cOuter, long cInner,
                  int hdiv,
                  const float* __restrict__ bias,
                  const int* __restrict__ ids, int idsStride)
{
    __shared__ uint32_t As[BM][SKA];
    __shared__ uint32_t Bs[BN][SKA];

    const int z  = blockIdx.z;
    const int bo = z / hdiv;
    const int hi = z - bo * hdiv;
    A += (long)bo * aOuter + (long)hi * aInner;
    B += (long)bo * bOuter + (long)hi * bInner;
    C += (long)bo * cOuter + (long)hi * cInner;
    if (EPI == 2) ids += (long)bo * idsStride;

    const int tid  = threadIdx.x;
    const int lane = tid & 31;
    const int wid  = tid >> 5;
    const int g    = lane >> 2;     // 0..7
    const int i4   = lane & 3;      // 0..3
    const int warp_m = wid >> 2;    // 0..1  (64 rows)
    const int warp_n = wid & 3;     // 0..3  (32 cols)

    const int m0 = blockIdx.y * BM;
    const int n0 = blockIdx.x * BN;

    // loader index mapping (A and NT-B): 128 rows x 8 float4 cols
    int ldRow[4], ldCol[4];   // row 0..127, k-offset (float4 start)
    int nnK[4],  nnC[4];      // NN-B: k row 0..31, n-offset
    #pragma unroll
    for (int u = 0; u < 4; u++) {
        int slot = tid + u * 256;
        ldRow[u] = slot >> 3;
        ldCol[u] = (slot & 7) * 4;
        nnK[u]   = slot >> 5;
        nnC[u]   = (slot & 31) * 4;
    }

    float acc[4][4][4];
    #pragma unroll
    for (int a = 0; a < 4; a++)
        #pragma unroll
        for (int b = 0; b < 4; b++)
            #pragma unroll
            for (int c = 0; c < 4; c++)
                acc[a][b][c] = 0.f;

    const int nK = K / BK;

    float4 aR[4], bR[4];
    // prefetch tile 0
    #pragma unroll
    for (int u = 0; u < 4; u++) {
        aR[u] = *(const float4*)(A + (long)(m0 + ldRow[u]) * lda + ldCol[u]);
        if (!B_NN)
            bR[u] = *(const float4*)(B + (long)(n0 + ldRow[u]) * ldb + ldCol[u]);
        else
            bR[u] = *(const float4*)(B + (long)nnK[u] * ldb + n0 + nnC[u]);
    }

    for (int kt = 0; kt < nK; kt++) {
        // commit prefetched regs to smem (tf32-rounded)
        #pragma unroll
        for (int u = 0; u < 4; u++) {
            float4 v = aR[u];
            uint4 t = make_uint4(to_tf32(v.x), to_tf32(v.y), to_tf32(v.z), to_tf32(v.w));
            *(uint4*)&As[ldRow[u]][ldCol[u]] = t;
        }
        if (!B_NN) {
            #pragma unroll
            for (int u = 0; u < 4; u++) {
                float4 v = bR[u];
                uint4 t = make_uint4(to_tf32(v.x), to_tf32(v.y), to_tf32(v.z), to_tf32(v.w));
                *(uint4*)&Bs[ldRow[u]][ldCol[u]] = t;
            }
        } else {
            #pragma unroll
            for (int u = 0; u < 4; u++) {
                float4 v = bR[u];
                Bs[nnC[u] + 0][nnK[u]] = to_tf32(v.x);
                Bs[nnC[u] + 1][nnK[u]] = to_tf32(v.y);
                Bs[nnC[u] + 2][nnK[u]] = to_tf32(v.z);
                Bs[nnC[u] + 3][nnK[u]] = to_tf32(v.w);
            }
        }
        __syncthreads();

        // prefetch next tile while computing
        if (kt + 1 < nK) {
            const int k0 = (kt + 1) * BK;
            #pragma unroll
            for (int u = 0; u < 4; u++) {
                aR[u] = *(const float4*)(A + (long)(m0 + ldRow[u]) * lda + k0 + ldCol[u]);
                if (!B_NN)
                    bR[u] = *(const float4*)(B + (long)(n0 + ldRow[u]) * ldb + k0 + ldCol[u]);
                else
                    bR[u] = *(const float4*)(B + (long)(k0 + nnK[u]) * ldb + n0 + nnC[u]);
            }
        }

        // compute: 4 k-steps of 8
        #pragma unroll
        for (int ks = 0; ks < 4; ks++) {
            const int k0 = ks * 8;
            uint32_t af[4][4], bf[4][2];
            #pragma unroll
            for (int mt = 0; mt < 4; mt++) {
                int mb = warp_m * 64 + mt * 16;
                af[mt][0] = As[mb + g    ][k0 + i4    ];
                af[mt][1] = As[mb + g + 8][k0 + i4    ];
                af[mt][2] = As[mb + g    ][k0 + i4 + 4];
                af[mt][3] = As[mb + g + 8][k0 + i4 + 4];
            }
            #pragma unroll
            for (int nt = 0; nt < 4; nt++) {
                int nb = warp_n * 32 + nt * 8;
                bf[nt][0] = Bs[nb + g][k0 + i4    ];
                bf[nt][1] = Bs[nb + g][k0 + i4 + 4];
            }
            #pragma unroll
            for (int mt = 0; mt < 4; mt++)
                #pragma unroll
                for (int nt = 0; nt < 4; nt++) {
                    float* c = acc[mt][nt];
                    asm volatile(
                        "mma.sync.aligned.m16n8k8.row.col.f32.tf32.tf32.f32 "
                        "{%0,%1,%2,%3}, {%4,%5,%6,%7}, {%8,%9}, {%0,%1,%2,%3};\n"
                        : "+f"(c[0]), "+f"(c[1]), "+f"(c[2]), "+f"(c[3])
                        : "r"(af[mt][0]), "r"(af[mt][1]), "r"(af[mt][2]), "r"(af[mt][3]),
                          "r"(bf[nt][0]), "r"(bf[nt][1]));
                }
        }
        __syncthreads();
    }

    // epilogue: c0 {g, 2i}, c1 {g, 2i+1}, c2 {g+8, 2i}, c3 {g+8, 2i+1}
    #pragma unroll
    for (int mt = 0; mt < 4; mt++) {
        int r0 = m0 + warp_m * 64 + mt * 16 + g;
        int r1 = r0 + 8;
        #pragma unroll
        for (int nt = 0; nt < 4; nt++) {
            int col = n0 + warp_n * 32 + nt * 8 + 2 * i4;
            float v0 = acc[mt][nt][0], v1 = acc[mt][nt][1];
            float v2 = acc[mt][nt][2], v3 = acc[mt][nt][3];
            if (EPI == 1) {
                float b0 = bias[col], b1 = bias[col + 1];
                v0 += b0; v1 += b1; v2 += b0; v3 += b1;
            }
            if (EPI == 2) {
                float bb0 = (float)ids[col]     * NEG_BIAS;
                float bb1 = (float)ids[col + 1] * NEG_BIAS;
                v0 = (v0 + bb0) * SCALE; v1 = (v1 + bb1) * SCALE;
                v2 = (v2 + bb0) * SCALE; v3 = (v3 + bb1) * SCALE;
            }
            *(float2*)(C + (long)r0 * ldc + col) = make_float2(v0, v1);
            *(float2*)(C + (long)r1 * ldc + col) = make_float2(v2, v3);
        }
    }
}

// ---------------- row softmax over 1024 columns -------------------------------
__global__ __launch_bounds__(256)
void softmax_kernel(float* __restrict__ S)
{
    const long row = blockIdx.x;
    float* p = S + row * (long)NS;
    const int tid = threadIdx.x;
    const int lane = tid & 31, wid = tid >> 5;

    float4 v = ((const float4*)p)[tid];

    float mx = fmaxf(fmaxf(v.x, v.y), fmaxf(v.z, v.w));
    #pragma unroll
    for (int o = 16; o; o >>= 1) mx = fmaxf(mx, __shfl_xor_sync(0xffffffffu, mx, o));
    __shared__ float red[8];
    if (lane == 0) red[wid] = mx;
    __syncthreads();
    float m = red[0];
    #pragma unroll
    for (int i = 1; i < 8; i++) m = fmaxf(m, red[i]);

    float4 e;
    e.x = __expf(v.x - m);
    e.y = __expf(v.y - m);
    e.z = __expf(v.z - m);
    e.w = __expf(v.w - m);

    float s = e.x + e.y + e.z + e.w;
    #pragma unroll
    for (int o = 16; o; o >>= 1) s += __shfl_xor_sync(0xffffffffu, s, o);
    __syncthreads();
    if (lane == 0) red[wid] = s;
    __syncthreads();
    float tot = red[0];
    #pragma unroll
    for (int i = 1; i < 8; i++) tot += red[i];

    float inv = 1.0f / tot;
    e.x *= inv; e.y *= inv; e.z *= inv; e.w *= inv;
    ((float4*)p)[tid] = e;
}

// ---------------- launch ------------------------------------------------------
extern "C" void kernel_launch(void* const* d_in, const int* in_sizes, int n_in,
                              void* d_out, int out_size)
{
    const float* x     = (const float*)d_in[0];   // [4,1024,2048]
    const int*   ids   = (const int*)  d_in[1];   // [4,1024]
    const float* w_in  = (const float*)d_in[2];   // [6144,2048]
    const float* w_out = (const float*)d_in[3];   // [2048,2048]
    const float* b_out = (const float*)d_in[4];   // [2048]
    float* out = (float*)d_out;                   // [4,1024,2048]

    void *p_qkv, *p_S, *p_ctx;
    cudaGetSymbolAddress(&p_qkv, g_qkv);
    cudaGetSymbolAddress(&p_S,   g_S);
    cudaGetSymbolAddress(&p_ctx, g_ctx);
    float* qkv = (float*)p_qkv;
    float* S   = (float*)p_S;
    float* ctx = (float*)p_ctx;

    // K1: QKV = x @ w_in^T   [4096,6144] = [4096,2048] x [6144,2048]^T
    tgemm_kernel<false, 0><<<dim3(E3 / BN, SEQ / BM, 1), 256>>>(
        x, w_in, qkv, D, D, D, E3,
        0, 0, 0, 0, 0, 0, 1, nullptr, nullptr, 0);

    // K2: S[b,h] = (Q K^T + mask) * scale   batched 64x
    tgemm_kernel<false, 2><<<dim3(NS / BN, NS / BM, BSZ * H), 256>>>(
        qkv, qkv + D, S,
        DH, E3, E3, NS,
        (long)NS * E3, DH,
        (long)NS * E3, DH,
        (long)H * NS * NS, (long)NS * NS,
        H, nullptr, ids, NS);

    // K3: row softmax
    softmax_kernel<<<BSZ * H * NS, 256>>>(S);

    // K4: ctx[b,h] = P @ V   batched 64x: [1024,128] = [1024,1024] x [1024,128]
    tgemm_kernel<true, 0><<<dim3(DH / BN, NS / BM, BSZ * H), 256>>>(
        S, qkv + 2 * D, ctx,
        NS, NS, E3, D,
        (long)H * NS * NS, (long)NS * NS,
        (long)NS * E3, DH,
        (long)NS * D, DH,
        H, nullptr, nullptr, 0);

    // K5: out = ctx @ w_out^T + b_out   [4096,2048] = [4096,2048] x [2048,2048]^T
    tgemm_kernel<false, 1><<<dim3(D / BN, SEQ / BM, 1), 256>>>(
        ctx, w_out, out, D, D, D, D,
        0, 0, 0, 0, 0, 0, 1, b_out, nullptr, 0);
}

// round 6
// speedup vs baseline: 3.4110x; 1.2810x over previous
#include <cuda_runtime.h>
#include <cuda_bf16.h>
#include <cstdint>

// Problem constants
#define BSZ 4
#define NS  1024
#define D   2048
#define H   16
#define DH  128
#define SEQ (BSZ*NS)          // 4096
#define E3  (3*D)             // 6144
#define SCALE 0.08838834764831845f   // DH^-0.5
#define NEG_BIAS (-1e9f)

// ---------------- scratch (global device arrays; no allocations) -------------
__device__ float g_qkv[SEQ * E3];                 // [4096, 6144]
__device__ float g_S[(long)BSZ * H * NS * NS];    // [64, 1024, 1024]
__device__ float g_ctx[SEQ * D];                  // [4096, 2048]

__device__ __forceinline__ uint32_t to_tf32(float x) {
    uint32_t r;
    asm("cvt.rna.tf32.f32 %0, %1;" : "=r"(r) : "f"(x));
    return r;
}

// ---------------- tf32 tensor-core GEMM, cp.async 3-stage pipeline ------------
// C[M,N] = A[M,K] * B
//   A: K-contiguous, leading dim lda
//   B_NN=false: B is [N,K] K-contiguous (NT), ldb = row stride
//   B_NN=true : B is [K,N] N-contiguous (NN), ldb = row stride
// EPI: 0 plain, 1 +bias[col], 2 (acc + ids[col]*-1e9)*scale
#define BM 128
#define BN 128
#define BK 32
#define STAGES 3
#define STAGE_FLOATS 8192          // A: 128*32, B: 4096 (either layout)
#define SMEM_BYTES (STAGES * STAGE_FLOATS * 4)   // 96 KB

template<bool B_NN, int EPI>
__global__ __launch_bounds__(256)
void tgemm_kernel(const float* __restrict__ A,
                  const float* __restrict__ B,
                  float* __restrict__ C,
                  int K, int lda, int ldb, int ldc,
                  long aOuter, long aInner,
                  long bOuter, long bInner,
                  long cOuter, long cInner,
                  int hdiv,
                  const float* __restrict__ bias,
                  const int* __restrict__ ids, int idsStride)
{
    extern __shared__ float sm[];

    const int z  = blockIdx.z;
    const int bo = z / hdiv;
    const int hi = z - bo * hdiv;
    A += (long)bo * aOuter + (long)hi * aInner;
    B += (long)bo * bOuter + (long)hi * bInner;
    C += (long)bo * cOuter + (long)hi * cInner;
    if (EPI == 2) ids += (long)bo * idsStride;

    const int tid  = threadIdx.x;
    const int lane = tid & 31;
    const int wid  = tid >> 5;
    const int g    = lane >> 2;     // 0..7
    const int i4   = lane & 3;      // 0..3
    const int warp_m = wid >> 2;    // 0..1  (64 rows)
    const int warp_n = wid & 3;     // 0..3  (32 cols)

    const int m0 = blockIdx.y * BM;
    const int n0 = blockIdx.x * BN;

    float acc[4][4][4];
    #pragma unroll
    for (int a = 0; a < 4; a++)
        #pragma unroll
        for (int b = 0; b < 4; b++)
            #pragma unroll
            for (int c = 0; c < 4; c++)
                acc[a][b][c] = 0.f;

    const int nK = K / BK;

    // producer: global -> smem via cp.async, XOR-swizzled (no padding)
    // A / NT-B element (row, k) stored at row*32 + (((k>>2) ^ (row&7))<<2) + (k&3)
    // NN-B  element (k, n)  stored at k*128 + (((n>>2) ^ (k&7))<<2) + (n&3)
    auto produce = [&](int st, int k0) {
        float* As = sm + st * STAGE_FLOATS;
        float* Bs = As + 4096;
        #pragma unroll
        for (int u = 0; u < 4; u++) {
            int slot = tid + u * 256;
            int row  = slot >> 3;
            int c4   = slot & 7;
            const float* srcA = A + (long)(m0 + row) * lda + k0 + c4 * 4;
            uint32_t dA = (uint32_t)__cvta_generic_to_shared(
                As + row * 32 + ((c4 ^ (row & 7)) << 2));
            asm volatile("cp.async.cg.shared.global [%0], [%1], 16;\n"
                         :: "r"(dA), "l"(srcA));
            if (!B_NN) {
                const float* srcB = B + (long)(n0 + row) * ldb + k0 + c4 * 4;
                uint32_t dB = (uint32_t)__cvta_generic_to_shared(
                    Bs + row * 32 + ((c4 ^ (row & 7)) << 2));
                asm volatile("cp.async.cg.shared.global [%0], [%1], 16;\n"
                             :: "r"(dB), "l"(srcB));
            } else {
                int kr = slot >> 5;      // 0..31
                int n4 = slot & 31;      // 0..31
                const float* srcB = B + (long)(k0 + kr) * ldb + n0 + n4 * 4;
                uint32_t dB = (uint32_t)__cvta_generic_to_shared(
                    Bs + kr * 128 + ((n4 ^ (kr & 7)) << 2));
                asm volatile("cp.async.cg.shared.global [%0], [%1], 16;\n"
                             :: "r"(dB), "l"(srcB));
            }
        }
    };

    auto compute = [&](int st) {
        const float* As = sm + st * STAGE_FLOATS;
        const float* Bs = As + 4096;
        #pragma unroll
        for (int ks = 0; ks < 4; ks++) {
            const int c0 = (((2 * ks)     ^ g) << 2) + i4;
            const int c1 = (((2 * ks + 1) ^ g) << 2) + i4;
            uint32_t af[4][4], bf[4][2];
            #pragma unroll
            for (int mt = 0; mt < 4; mt++) {
                int r = warp_m * 64 + mt * 16 + g;
                af[mt][0] = to_tf32(As[r * 32 + c0]);
                af[mt][1] = to_tf32(As[(r + 8) * 32 + c0]);
                af[mt][2] = to_tf32(As[r * 32 + c1]);
                af[mt][3] = to_tf32(As[(r + 8) * 32 + c1]);
            }
            if (!B_NN) {
                #pragma unroll
                for (int nt = 0; nt < 4; nt++) {
                    int rn = warp_n * 32 + nt * 8 + g;
                    bf[nt][0] = to_tf32(Bs[rn * 32 + c0]);
                    bf[nt][1] = to_tf32(Bs[rn * 32 + c1]);
                }
            } else {
                #pragma unroll
                for (int nt = 0; nt < 4; nt++) {
                    int n  = warp_n * 32 + nt * 8 + g;
                    int ng = n >> 2, nw = n & 3;
                    bf[nt][0] = to_tf32(Bs[(8 * ks + i4) * 128 +
                                           ((ng ^ i4) << 2) + nw]);
                    bf[nt][1] = to_tf32(Bs[(8 * ks + i4 + 4) * 128 +
                                           ((ng ^ (i4 + 4)) << 2) + nw]);
                }
            }
            #pragma unroll
            for (int mt = 0; mt < 4; mt++)
                #pragma unroll
                for (int nt = 0; nt < 4; nt++) {
                    float* c = acc[mt][nt];
                    asm volatile(
                        "mma.sync.aligned.m16n8k8.row.col.f32.tf32.tf32.f32 "
                        "{%0,%1,%2,%3}, {%4,%5,%6,%7}, {%8,%9}, {%0,%1,%2,%3};\n"
                        : "+f"(c[0]), "+f"(c[1]), "+f"(c[2]), "+f"(c[3])
                        : "r"(af[mt][0]), "r"(af[mt][1]), "r"(af[mt][2]), "r"(af[mt][3]),
                          "r"(bf[nt][0]), "r"(bf[nt][1]));
                }
        }
    };

    // prologue: stages 0 and 1 in flight
    produce(0, 0);
    asm volatile("cp.async.commit_group;\n" ::: "memory");
    if (nK > 1) produce(1, BK);
    asm volatile("cp.async.commit_group;\n" ::: "memory");

    for (int kt = 0; kt < nK; kt++) {
        asm volatile("cp.async.wait_group 1;\n" ::: "memory");
        __syncthreads();
        if (kt + 2 < nK) produce((kt + 2) % STAGES, (kt + 2) * BK);
        asm volatile("cp.async.commit_group;\n" ::: "memory");
        compute(kt % STAGES);
        // next iteration's wait+sync protects buffer reuse
        if (kt + 1 < nK) __syncthreads();
    }

    // epilogue: c0 {g, 2i}, c1 {g, 2i+1}, c2 {g+8, 2i}, c3 {g+8, 2i+1}
    #pragma unroll
    for (int mt = 0; mt < 4; mt++) {
        int r0 = m0 + warp_m * 64 + mt * 16 + g;
        int r1 = r0 + 8;
        #pragma unroll
        for (int nt = 0; nt < 4; nt++) {
            int col = n0 + warp_n * 32 + nt * 8 + 2 * i4;
            float v0 = acc[mt][nt][0], v1 = acc[mt][nt][1];
            float v2 = acc[mt][nt][2], v3 = acc[mt][nt][3];
            if (EPI == 1) {
                float b0 = bias[col], b1 = bias[col + 1];
                v0 += b0; v1 += b1; v2 += b0; v3 += b1;
            }
            if (EPI == 2) {
                float bb0 = (float)ids[col]     * NEG_BIAS;
                float bb1 = (float)ids[col + 1] * NEG_BIAS;
                v0 = (v0 + bb0) * SCALE; v1 = (v1 + bb1) * SCALE;
                v2 = (v2 + bb0) * SCALE; v3 = (v3 + bb1) * SCALE;
            }
            *(float2*)(C + (long)r0 * ldc + col) = make_float2(v0, v1);
            *(float2*)(C + (long)r1 * ldc + col) = make_float2(v2, v3);
        }
    }
}

// ---------------- row softmax over 1024 columns -------------------------------
__global__ __launch_bounds__(256)
void softmax_kernel(float* __restrict__ S)
{
    const long row = blockIdx.x;
    float* p = S + row * (long)NS;
    const int tid = threadIdx.x;
    const int lane = tid & 31, wid = tid >> 5;

    float4 v = ((const float4*)p)[tid];

    float mx = fmaxf(fmaxf(v.x, v.y), fmaxf(v.z, v.w));
    #pragma unroll
    for (int o = 16; o; o >>= 1) mx = fmaxf(mx, __shfl_xor_sync(0xffffffffu, mx, o));
    __shared__ float red[8];
    if (lane == 0) red[wid] = mx;
    __syncthreads();
    float m = red[0];
    #pragma unroll
    for (int i = 1; i < 8; i++) m = fmaxf(m, red[i]);

    float4 e;
    e.x = __expf(v.x - m);
    e.y = __expf(v.y - m);
    e.z = __expf(v.z - m);
    e.w = __expf(v.w - m);

    float s = e.x + e.y + e.z + e.w;
    #pragma unroll
    for (int o = 16; o; o >>= 1) s += __shfl_xor_sync(0xffffffffu, s, o);
    __syncthreads();
    if (lane == 0) red[wid] = s;
    __syncthreads();
    float tot = red[0];
    #pragma unroll
    for (int i = 1; i < 8; i++) tot += red[i];

    float inv = 1.0f / tot;
    e.x *= inv; e.y *= inv; e.z *= inv; e.w *= inv;
    ((float4*)p)[tid] = e;
}

// ---------------- launch ------------------------------------------------------
extern "C" void kernel_launch(void* const* d_in, const int* in_sizes, int n_in,
                              void* d_out, int out_size)
{
    const float* x     = (const float*)d_in[0];   // [4,1024,2048]
    const int*   ids   = (const int*)  d_in[1];   // [4,1024]
    const float* w_in  = (const float*)d_in[2];   // [6144,2048]
    const float* w_out = (const float*)d_in[3];   // [2048,2048]
    const float* b_out = (const float*)d_in[4];   // [2048]
    float* out = (float*)d_out;                   // [4,1024,2048]

    void *p_qkv, *p_S, *p_ctx;
    cudaGetSymbolAddress(&p_qkv, g_qkv);
    cudaGetSymbolAddress(&p_S,   g_S);
    cudaGetSymbolAddress(&p_ctx, g_ctx);
    float* qkv = (float*)p_qkv;
    float* S   = (float*)p_S;
    float* ctx = (float*)p_ctx;

    // raise dynamic smem limit (idempotent; host-side, capture-safe)
    cudaFuncSetAttribute(tgemm_kernel<false, 0>,
                         cudaFuncAttributeMaxDynamicSharedMemorySize, SMEM_BYTES);
    cudaFuncSetAttribute(tgemm_kernel<false, 1>,
                         cudaFuncAttributeMaxDynamicSharedMemorySize, SMEM_BYTES);
    cudaFuncSetAttribute(tgemm_kernel<false, 2>,
                         cudaFuncAttributeMaxDynamicSharedMemorySize, SMEM_BYTES);
    cudaFuncSetAttribute(tgemm_kernel<true, 0>,
                         cudaFuncAttributeMaxDynamicSharedMemorySize, SMEM_BYTES);

    // K1: QKV = x @ w_in^T   [4096,6144] = [4096,2048] x [6144,2048]^T
    tgemm_kernel<false, 0><<<dim3(E3 / BN, SEQ / BM, 1), 256, SMEM_BYTES>>>(
        x, w_in, qkv, D, D, D, E3,
        0, 0, 0, 0, 0, 0, 1, nullptr, nullptr, 0);

    // K2: S[b,h] = (Q K^T + mask) * scale   batched 64x
    tgemm_kernel<false, 2><<<dim3(NS / BN, NS / BM, BSZ * H), 256, SMEM_BYTES>>>(
        qkv, qkv + D, S,
        DH, E3, E3, NS,
        (long)NS * E3, DH,
        (long)NS * E3, DH,
        (long)H * NS * NS, (long)NS * NS,
        H, nullptr, ids, NS);

    // K3: row softmax
    softmax_kernel<<<BSZ * H * NS, 256>>>(S);

    // K4: ctx[b,h] = P @ V   batched 64x: [1024,128] = [1024,1024] x [1024,128]
    tgemm_kernel<true, 0><<<dim3(DH / BN, NS / BM, BSZ * H), 256, SMEM_BYTES>>>(
        S, qkv + 2 * D, ctx,
        NS, NS, E3, D,
        (long)H * NS * NS, (long)NS * NS,
        (long)NS * E3, DH,
        (long)NS * D, DH,
        H, nullptr, nullptr, 0);

    // K5: out = ctx @ w_out^T + b_out   [4096,2048] = [4096,2048] x [2048,2048]^T
    tgemm_kernel<false, 1><<<dim3(D / BN, SEQ / BM, 1), 256, SMEM_BYTES>>>(
        ctx, w_out, out, D, D, D, D,
        0, 0, 0, 0, 0, 0, 1, b_out, nullptr, 0);
}

// round 7
// speedup vs baseline: 3.9027x; 1.1442x over previous
#include <cuda_runtime.h>
#include <cuda_bf16.h>
#include <cstdint>

// Problem constants
#define BSZ 4
#define NS  1024
#define D   2048
#define H   16
#define DH  128
#define SEQ (BSZ*NS)          // 4096
#define E3  (3*D)             // 6144
#define SCALE 0.08838834764831845f   // DH^-0.5
#define NEG_BIAS (-1e9f)

// ---------------- scratch (global device arrays; no allocations) -------------
__device__ float g_qkv[SEQ * E3];                 // [4096, 6144] tf32-rounded
__device__ float g_S[(long)BSZ * H * NS * NS];    // [64, 1024, 1024]
__device__ float g_ctx[SEQ * D];                  // [4096, 2048] tf32-rounded
__device__ float g_xr[SEQ * D];                   // tf32-rounded x
__device__ float g_winr[E3 * D];                  // tf32-rounded w_in
__device__ float g_woutr[D * D];                  // tf32-rounded w_out

__device__ __forceinline__ uint32_t to_tf32(float x) {
    uint32_t r;
    asm("cvt.rna.tf32.f32 %0, %1;" : "=r"(r) : "f"(x));
    return r;
}
__device__ __forceinline__ float round_tf32f(float x) {
    return __uint_as_float(to_tf32(x));
}

// ---------------- elementwise tf32 pre-round ----------------------------------
__global__ __launch_bounds__(256)
void round_tf32_kernel(const float* __restrict__ in, float* __restrict__ out, long n4)
{
    long i = blockIdx.x * (long)blockDim.x + threadIdx.x;
    long stride = (long)gridDim.x * blockDim.x;
    for (; i < n4; i += stride) {
        float4 v = ((const float4*)in)[i];
        v.x = round_tf32f(v.x); v.y = round_tf32f(v.y);
        v.z = round_tf32f(v.z); v.w = round_tf32f(v.w);
        ((float4*)out)[i] = v;
    }
}

// ---------------- tf32 tensor-core GEMM, cp.async 3-stage pipeline ------------
// Inputs must already be tf32-rounded. No cvt in the mainloop.
// C[M,N] = A[M,K] * B
//   A: K-contiguous, leading dim lda
//   B_NN=false: B is [N,K] K-contiguous (NT), ldb = row stride
//   B_NN=true : B is [K,N] N-contiguous (NN), ldb = row stride
// EPI: 0 plain, 1 +bias[col], 2 (acc + ids[col]*-1e9)*scale
// ROUND: round outputs to tf32 (for tensors consumed by later GEMMs)
#define BM 128
#define BN 128
#define BK 32
#define STAGES 3
#define STAGE_FLOATS 8192          // A: 128*32, B: 4096 (either layout)
#define SMEM_BYTES (STAGES * STAGE_FLOATS * 4)   // 96 KB

template<bool B_NN, int EPI, bool ROUND>
__global__ __launch_bounds__(256)
void tgemm_kernel(const float* __restrict__ A,
                  const float* __restrict__ B,
                  float* __restrict__ C,
                  int K, int lda, int ldb, int ldc,
                  long aOuter, long aInner,
                  long bOuter, long bInner,
                  long cOuter, long cInner,
                  int hdiv,
                  const float* __restrict__ bias,
                  const int* __restrict__ ids, int idsStride)
{
    extern __shared__ float sm[];

    const int z  = blockIdx.z;
    const int bo = z / hdiv;
    const int hi = z - bo * hdiv;
    A += (long)bo * aOuter + (long)hi * aInner;
    B += (long)bo * bOuter + (long)hi * bInner;
    C += (long)bo * cOuter + (long)hi * cInner;
    if (EPI == 2) ids += (long)bo * idsStride;

    const int tid  = threadIdx.x;
    const int lane = tid & 31;
    const int wid  = tid >> 5;
    const int g    = lane >> 2;     // 0..7
    const int i4   = lane & 3;      // 0..3
    const int warp_m = wid >> 2;    // 0..1  (64 rows)
    const int warp_n = wid & 3;     // 0..3  (32 cols)

    const int m0 = blockIdx.y * BM;
    const int n0 = blockIdx.x * BN;

    float acc[4][4][4];
    #pragma unroll
    for (int a = 0; a < 4; a++)
        #pragma unroll
        for (int b = 0; b < 4; b++)
            #pragma unroll
            for (int c = 0; c < 4; c++)
                acc[a][b][c] = 0.f;

    const int nK = K / BK;

    // producer: global -> smem via cp.async, XOR-swizzled (no padding)
    // A / NT-B element (row, k) at row*32 + (((k>>2) ^ (row&7))<<2) + (k&3)
    // NN-B  element (k, n)  at k*128 + (((n>>2) ^ (k&7))<<2) + (n&3)
    auto produce = [&](int st, int k0) {
        float* As = sm + st * STAGE_FLOATS;
        float* Bs = As + 4096;
        #pragma unroll
        for (int u = 0; u < 4; u++) {
            int slot = tid + u * 256;
            int row  = slot >> 3;
            int c4   = slot & 7;
            const float* srcA = A + (long)(m0 + row) * lda + k0 + c4 * 4;
            uint32_t dA = (uint32_t)__cvta_generic_to_shared(
                As + row * 32 + ((c4 ^ (row & 7)) << 2));
            asm volatile("cp.async.cg.shared.global [%0], [%1], 16;\n"
                         :: "r"(dA), "l"(srcA));
            if (!B_NN) {
                const float* srcB = B + (long)(n0 + row) * ldb + k0 + c4 * 4;
                uint32_t dB = (uint32_t)__cvta_generic_to_shared(
                    Bs + row * 32 + ((c4 ^ (row & 7)) << 2));
                asm volatile("cp.async.cg.shared.global [%0], [%1], 16;\n"
                             :: "r"(dB), "l"(srcB));
            } else {
                int kr = slot >> 5;      // 0..31
                int n4 = slot & 31;      // 0..31
                const float* srcB = B + (long)(k0 + kr) * ldb + n0 + n4 * 4;
                uint32_t dB = (uint32_t)__cvta_generic_to_shared(
                    Bs + kr * 128 + ((n4 ^ (kr & 7)) << 2));
                asm volatile("cp.async.cg.shared.global [%0], [%1], 16;\n"
                             :: "r"(dB), "l"(srcB));
            }
        }
    };

    uint32_t af[2][4][4], bf[2][4][2];

    // fragment loader for k-step ks of stage st -> buffer p
    auto load_frags = [&](int st, int ks, int p) {
        const uint32_t* As = (const uint32_t*)(sm + st * STAGE_FLOATS);
        const uint32_t* Bs = As + 4096;
        const int c0 = (((2 * ks)     ^ g) << 2) + i4;
        const int c1 = (((2 * ks + 1) ^ g) << 2) + i4;
        #pragma unroll
        for (int mt = 0; mt < 4; mt++) {
            int r = warp_m * 64 + mt * 16 + g;
            af[p][mt][0] = As[r * 32 + c0];
            af[p][mt][1] = As[(r + 8) * 32 + c0];
            af[p][mt][2] = As[r * 32 + c1];
            af[p][mt][3] = As[(r + 8) * 32 + c1];
        }
        if (!B_NN) {
            #pragma unroll
            for (int nt = 0; nt < 4; nt++) {
                int rn = warp_n * 32 + nt * 8 + g;
                bf[p][nt][0] = Bs[rn * 32 + c0];
                bf[p][nt][1] = Bs[rn * 32 + c1];
            }
        } else {
            #pragma unroll
            for (int nt = 0; nt < 4; nt++) {
                int n  = warp_n * 32 + nt * 8 + g;
                int ng = n >> 2, nw = n & 3;
                bf[p][nt][0] = Bs[(8 * ks + i4) * 128 + ((ng ^ i4) << 2) + nw];
                bf[p][nt][1] = Bs[(8 * ks + i4 + 4) * 128 + ((ng ^ (i4 + 4)) << 2) + nw];
            }
        }
    };

    auto mma_step = [&](int p) {
        #pragma unroll
        for (int mt = 0; mt < 4; mt++)
            #pragma unroll
            for (int nt = 0; nt < 4; nt++) {
                float* c = acc[mt][nt];
                asm volatile(
                    "mma.sync.aligned.m16n8k8.row.col.f32.tf32.tf32.f32 "
                    "{%0,%1,%2,%3}, {%4,%5,%6,%7}, {%8,%9}, {%0,%1,%2,%3};\n"
                    : "+f"(c[0]), "+f"(c[1]), "+f"(c[2]), "+f"(c[3])
                    : "r"(af[p][mt][0]), "r"(af[p][mt][1]),
                      "r"(af[p][mt][2]), "r"(af[p][mt][3]),
                      "r"(bf[p][nt][0]), "r"(bf[p][nt][1]));
            }
    };

    // prologue: stages 0 and 1 in flight
    produce(0, 0);
    asm volatile("cp.async.commit_group;\n" ::: "memory");
    if (nK > 1) produce(1, BK);
    asm volatile("cp.async.commit_group;\n" ::: "memory");

    for (int kt = 0; kt < nK; kt++) {
        asm volatile("cp.async.wait_group 1;\n" ::: "memory");
        __syncthreads();
        if (kt + 2 < nK) produce((kt + 2) % STAGES, (kt + 2) * BK);
        asm volatile("cp.async.commit_group;\n" ::: "memory");

        const int st = kt % STAGES;
        load_frags(st, 0, 0);
        #pragma unroll
        for (int ks = 0; ks < 4; ks++) {
            if (ks < 3) load_frags(st, ks + 1, (ks + 1) & 1);
            mma_step(ks & 1);
        }
        if (kt + 1 < nK) __syncthreads();
    }

    // epilogue: c0 {g, 2i}, c1 {g, 2i+1}, c2 {g+8, 2i}, c3 {g+8, 2i+1}
    #pragma unroll
    for (int mt = 0; mt < 4; mt++) {
        int r0 = m0 + warp_m * 64 + mt * 16 + g;
        int r1 = r0 + 8;
        #pragma unroll
        for (int nt = 0; nt < 4; nt++) {
            int col = n0 + warp_n * 32 + nt * 8 + 2 * i4;
            float v0 = acc[mt][nt][0], v1 = acc[mt][nt][1];
            float v2 = acc[mt][nt][2], v3 = acc[mt][nt][3];
            if (EPI == 1) {
                float b0 = bias[col], b1 = bias[col + 1];
                v0 += b0; v1 += b1; v2 += b0; v3 += b1;
            }
            if (EPI == 2) {
                float bb0 = (float)ids[col]     * NEG_BIAS;
                float bb1 = (float)ids[col + 1] * NEG_BIAS;
                v0 = (v0 + bb0) * SCALE; v1 = (v1 + bb1) * SCALE;
                v2 = (v2 + bb0) * SCALE; v3 = (v3 + bb1) * SCALE;
            }
            if (ROUND) {
                v0 = round_tf32f(v0); v1 = round_tf32f(v1);
                v2 = round_tf32f(v2); v3 = round_tf32f(v3);
            }
            *(float2*)(C + (long)r0 * ldc + col) = make_float2(v0, v1);
            *(float2*)(C + (long)r1 * ldc + col) = make_float2(v2, v3);
        }
    }
}

// ---------------- row softmax over 1024 columns (tf32-rounded probs) ----------
__global__ __launch_bounds__(256)
void softmax_kernel(float* __restrict__ S)
{
    const long row = blockIdx.x;
    float* p = S + row * (long)NS;
    const int tid = threadIdx.x;
    const int lane = tid & 31, wid = tid >> 5;

    float4 v = ((const float4*)p)[tid];

    float mx = fmaxf(fmaxf(v.x, v.y), fmaxf(v.z, v.w));
    #pragma unroll
    for (int o = 16; o; o >>= 1) mx = fmaxf(mx, __shfl_xor_sync(0xffffffffu, mx, o));
    __shared__ float red[8];
    if (lane == 0) red[wid] = mx;
    __syncthreads();
    float m = red[0];
    #pragma unroll
    for (int i = 1; i < 8; i++) m = fmaxf(m, red[i]);

    float4 e;
    e.x = __expf(v.x - m);
    e.y = __expf(v.y - m);
    e.z = __expf(v.z - m);
    e.w = __expf(v.w - m);

    float s = e.x + e.y + e.z + e.w;
    #pragma unroll
    for (int o = 16; o; o >>= 1) s += __shfl_xor_sync(0xffffffffu, s, o);
    __syncthreads();
    if (lane == 0) red[wid] = s;
    __syncthreads();
    float tot = red[0];
    #pragma unroll
    for (int i = 1; i < 8; i++) tot += red[i];

    float inv = 1.0f / tot;
    e.x = round_tf32f(e.x * inv);
    e.y = round_tf32f(e.y * inv);
    e.z = round_tf32f(e.z * inv);
    e.w = round_tf32f(e.w * inv);
    ((float4*)p)[tid] = e;
}

// ---------------- launch ------------------------------------------------------
extern "C" void kernel_launch(void* const* d_in, const int* in_sizes, int n_in,
                              void* d_out, int out_size)
{
    const float* x     = (const float*)d_in[0];   // [4,1024,2048]
    const int*   ids   = (const int*)  d_in[1];   // [4,1024]
    const float* w_in  = (const float*)d_in[2];   // [6144,2048]
    const float* w_out = (const float*)d_in[3];   // [2048,2048]
    const float* b_out = (const float*)d_in[4];   // [2048]
    float* out = (float*)d_out;                   // [4,1024,2048]

    void *p_qkv, *p_S, *p_ctx, *p_xr, *p_winr, *p_woutr;
    cudaGetSymbolAddress(&p_qkv,  g_qkv);
    cudaGetSymbolAddress(&p_S,    g_S);
    cudaGetSymbolAddress(&p_ctx,  g_ctx);
    cudaGetSymbolAddress(&p_xr,   g_xr);
    cudaGetSymbolAddress(&p_winr, g_winr);
    cudaGetSymbolAddress(&p_woutr,g_woutr);
    float* qkv   = (float*)p_qkv;
    float* S     = (float*)p_S;
    float* ctx   = (float*)p_ctx;
    float* xr    = (float*)p_xr;
    float* winr  = (float*)p_winr;
    float* woutr = (float*)p_woutr;

    cudaFuncSetAttribute(tgemm_kernel<false, 0, true>,
                         cudaFuncAttributeMaxDynamicSharedMemorySize, SMEM_BYTES);
    cudaFuncSetAttribute(tgemm_kernel<false, 1, false>,
                         cudaFuncAttributeMaxDynamicSharedMemorySize, SMEM_BYTES);
    cudaFuncSetAttribute(tgemm_kernel<false, 2, false>,
                         cudaFuncAttributeMaxDynamicSharedMemorySize, SMEM_BYTES);
    cudaFuncSetAttribute(tgemm_kernel<true, 0, true>,
                         cudaFuncAttributeMaxDynamicSharedMemorySize, SMEM_BYTES);

    // K0: pre-round x, w_in, w_out to tf32
    round_tf32_kernel<<<512, 256>>>(x,     xr,    (long)SEQ * D / 4);
    round_tf32_kernel<<<512, 256>>>(w_in,  winr,  (long)E3 * D / 4);
    round_tf32_kernel<<<512, 256>>>(w_out, woutr, (long)D * D / 4);

    // K1: QKV = x @ w_in^T   [4096,6144] = [4096,2048] x [6144,2048]^T  (round out)
    tgemm_kernel<false, 0, true><<<dim3(E3 / BN, SEQ / BM, 1), 256, SMEM_BYTES>>>(
        xr, winr, qkv, D, D, D, E3,
        0, 0, 0, 0, 0, 0, 1, nullptr, nullptr, 0);

    // K2: S[b,h] = (Q K^T + mask) * scale   batched 64x
    tgemm_kernel<false, 2, false><<<dim3(NS / BN, NS / BM, BSZ * H), 256, SMEM_BYTES>>>(
        qkv, qkv + D, S,
        DH, E3, E3, NS,
        (long)NS * E3, DH,
        (long)NS * E3, DH,
        (long)H * NS * NS, (long)NS * NS,
        H, nullptr, ids, NS);

    // K3: row softmax (rounds probs to tf32)
    softmax_kernel<<<BSZ * H * NS, 256>>>(S);

    // K4: ctx[b,h] = P @ V   batched 64x  (round out)
    tgemm_kernel<true, 0, true><<<dim3(DH / BN, NS / BM, BSZ * H), 256, SMEM_BYTES>>>(
        S, qkv + 2 * D, ctx,
        NS, NS, E3, D,
        (long)H * NS * NS, (long)NS * NS,
        (long)NS * E3, DH,
        (long)NS * D, DH,
        H, nullptr, nullptr, 0);

    // K5: out = ctx @ w_out^T + b_out   [4096,2048] = [4096,2048] x [2048,2048]^T
    tgemm_kernel<false, 1, false><<<dim3(D / BN, SEQ / BM, 1), 256, SMEM_BYTES>>>(
        ctx, woutr, out, D, D, D, D,
        0, 0, 0, 0, 0, 0, 1, b_out, nullptr, 0);
}